// round 15
// baseline (speedup 1.0000x reference)
#include <cuda_runtime.h>
#include <cuda_fp16.h>
#include <math.h>
#include <stdint.h>

#define NTOK 16384
#define DDIM 2048
#define NE   64
#define TOPK 8
#define TOPG 4
#define NGRP 8
#define TB   64
#define NB   (NTOK / TB)           /* 256 CTAs */
#define KT   64
#define NTILE (DDIM / KT)
#define RW   36                    /* row stride in u32 (144 B) */
#define APL  (TB * RW)             /* A plane u32 = 2304 */
#define BPL  (64 * RW)             /* B plane u32 = 2304 */
#define BUFU (2 * APL + 2 * BPL)   /* 9216 u32 per buffer */
#define SMEM_BYTES (2 * BUFU * 4)  /* 73728 */

#define ETAU 2.0e-5f
#define GTAU 5.0e-5f

#define XSR2 2052
#define WSR2 260
#define RSM_BYTES ((4 * XSR2 + 64 * WSR2) * 4)  /* 99392 */

__device__ uint32_t g_wH[NTILE][2][NE][32];
__device__ unsigned int g_redo_cnt;
__device__ unsigned int g_redo[NTOK];

/* ---------------- helpers ---------------- */
__device__ __forceinline__ uint32_t smem_u32(const void* p) {
    uint32_t a;
    asm("{ .reg .u64 t; cvta.to.shared.u64 t, %1; cvt.u32.u64 %0, t; }" : "=r"(a) : "l"(p));
    return a;
}
__device__ __forceinline__ void split2h(float a, float b, uint32_t& s0, uint32_t& s1) {
    __half2 h0 = __floats2half2_rn(a, b);
    float2 f0 = __half22float2(h0);
    __half2 h1 = __floats2half2_rn(a - f0.x, b - f0.y);
    s0 = *reinterpret_cast<uint32_t*>(&h0);
    s1 = *reinterpret_cast<uint32_t*>(&h1);
}
__device__ __forceinline__ void ldm4(uint32_t* r, uint32_t addr) {
    asm volatile("ldmatrix.sync.aligned.m8n8.x4.shared.b16 {%0,%1,%2,%3}, [%4];"
        : "=r"(r[0]), "=r"(r[1]), "=r"(r[2]), "=r"(r[3]) : "r"(addr));
}
__device__ __forceinline__ void mma16816(float* d, const uint32_t* a, const uint32_t* b) {
    asm volatile("mma.sync.aligned.m16n8k16.row.col.f32.f16.f16.f32 "
        "{%0,%1,%2,%3}, {%4,%5,%6,%7}, {%8,%9}, {%0,%1,%2,%3};"
        : "+f"(d[0]), "+f"(d[1]), "+f"(d[2]), "+f"(d[3])
        : "r"(a[0]), "r"(a[1]), "r"(a[2]), "r"(a[3]), "r"(b[0]), "r"(b[1]));
}

/* ------------- W split precompute (+ counter reset) ------------- */
__global__ void __launch_bounds__(256) wsplit_kernel(const float* __restrict__ W) {
    if (blockIdx.x == 0 && threadIdx.x == 0) g_redo_cnt = 0;
    int i = blockIdx.x * 256 + threadIdx.x;
    int e = i >> 10, kp = i & 1023;
    float2 ab = *reinterpret_cast<const float2*>(W + (size_t)e * DDIM + 2 * kp);
    uint32_t s0, s1;
    split2h(ab.x, ab.y, s0, s1);
    int t = kp >> 5, kl = kp & 31;
    g_wH[t][0][e][kl] = s0;
    g_wH[t][1][e][kl] = s1;
}

/* ------------- fast path: fp16-split mma GEMM, TB=64, 2 CTAs/SM ------------- */
__global__ void __launch_bounds__(256, 2) gate_gemm(
    const float* __restrict__ x, const float* __restrict__ bvec,
    const float* __restrict__ bias, float* __restrict__ out)
{
    extern __shared__ uint32_t sm[];
    const uint32_t smb = smem_u32(sm);
    const int tid = threadIdx.x;
    const int lane = tid & 31, wid = tid >> 5;
    const int t0 = blockIdx.x * TB;

    /* loaders: x = 4 chunks (64 rows x 16 quads), W = 4 chunks */
    const float4* xp[4];
    int aoff[4];
#pragma unroll
    for (int j = 0; j < 4; j++) {
        int idx = tid + j * 256;        /* 0..1023 */
        int r = idx >> 4, q = idx & 15;
        xp[j] = reinterpret_cast<const float4*>(x + (size_t)(t0 + r) * DDIM + 4 * q);
        aoff[j] = r * RW + 2 * q;
    }
    const uint4* wb = reinterpret_cast<const uint4*>(&g_wH[0][0][0][0]);
    int boff[4];
#pragma unroll
    for (int c = 0; c < 4; c++) {
        int idx = 4 * tid + 1024 * c;
        int s = idx >> 11, e = (idx >> 5) & 63, kp = idx & 31;
        boff[c] = 2 * APL + s * BPL + e * RW + kp;
    }

    /* warp tiling: mg = token block (16), ng = expert half (32) */
    const int mg = wid >> 1, ng = wid & 1;
    const uint32_t aLM0 = smb + (uint32_t)(lane & 15) * 144u + (uint32_t)(lane >> 4) * 16u;
    const uint32_t bLM0 = smb + 2u * APL * 4u + (uint32_t)((lane >> 4) & 1) * 1152u
                        + (uint32_t)(lane & 7) * 144u + (uint32_t)((lane >> 3) & 1) * 16u;

    float acc[4][4];
#pragma unroll
    for (int n = 0; n < 4; n++)
#pragma unroll
        for (int q = 0; q < 4; q++) acc[n][q] = 0.0f;

    float4 xv[4]; uint4 wv[4];
#pragma unroll
    for (int j = 0; j < 4; j++) xv[j] = xp[j][0];
#pragma unroll
    for (int c = 0; c < 4; c++) wv[c] = wb[tid + 256 * c];

    /* STS tile 0 -> buf0 */
    {
        uint32_t* bp = sm;
#pragma unroll
        for (int j = 0; j < 4; j++) {
            uint32_t p0, p1, q0, q1;
            split2h(xv[j].x, xv[j].y, p0, p1);
            split2h(xv[j].z, xv[j].w, q0, q1);
            uint32_t* ap = bp + aoff[j];
            *reinterpret_cast<uint2*>(ap)       = make_uint2(p0, q0);
            *reinterpret_cast<uint2*>(ap + APL) = make_uint2(p1, q1);
        }
#pragma unroll
        for (int c = 0; c < 4; c++)
            *reinterpret_cast<uint4*>(bp + boff[c]) = wv[c];
    }
    __syncthreads();

#pragma unroll 1
    for (int t = 0; t < NTILE; t++) {
        const int cur = t & 1;
        const uint32_t bofs = (uint32_t)cur * (BUFU * 4u);

        if (t + 1 < NTILE) {
#pragma unroll
            for (int j = 0; j < 4; j++) { xp[j] += 16; xv[j] = xp[j][0]; }
            const uint4* wbt = wb + (size_t)(t + 1) * 1024;
#pragma unroll
            for (int c = 0; c < 4; c++) wv[c] = wbt[tid + 256 * c];
        }

#pragma unroll
        for (int k16 = 0; k16 < 4; k16++) {
            uint32_t a[2][4];
#pragma unroll
            for (int s = 0; s < 2; s++)
                ldm4(a[s], aLM0 + bofs + (uint32_t)s * (APL * 4u)
                          + (uint32_t)(mg * 16) * 144u + (uint32_t)k16 * 32u);
            uint32_t b[4][2][2];
#pragma unroll
            for (int p = 0; p < 2; p++)
#pragma unroll
                for (int s = 0; s < 2; s++) {
                    uint32_t r[4];
                    ldm4(r, bLM0 + bofs + (uint32_t)s * (BPL * 4u)
                           + (uint32_t)(ng * 4 + 2 * p) * 1152u + (uint32_t)k16 * 32u);
                    b[2 * p][s][0] = r[0]; b[2 * p][s][1] = r[1];
                    b[2 * p + 1][s][0] = r[2]; b[2 * p + 1][s][1] = r[3];
                }
#pragma unroll
            for (int n = 0; n < 4; n++) {
                float* d = acc[n];
                mma16816(d, a[0], b[n][0]);
                mma16816(d, a[0], b[n][1]);
                mma16816(d, a[1], b[n][0]);
            }
        }

        if (t + 1 < NTILE) {
            uint32_t* bp = sm + (1 - cur) * BUFU;
#pragma unroll
            for (int j = 0; j < 4; j++) {
                uint32_t p0, p1, q0, q1;
                split2h(xv[j].x, xv[j].y, p0, p1);
                split2h(xv[j].z, xv[j].w, q0, q1);
                uint32_t* ap = bp + aoff[j];
                *reinterpret_cast<uint2*>(ap)       = make_uint2(p0, q0);
                *reinterpret_cast<uint2*>(ap + APL) = make_uint2(p1, q1);
            }
#pragma unroll
            for (int c = 0; c < 4; c++)
                *reinterpret_cast<uint4*>(bp + boff[c]) = wv[c];
        }
        __syncthreads();
    }

    /* logits -> sc[token][expert], stride 66 (64*66 = 4224 floats) */
    float* sc = reinterpret_cast<float*>(sm);
    {
        const int g = lane >> 2, c2 = 2 * (lane & 3);
#pragma unroll
        for (int n = 0; n < 4; n++) {
            int tt = mg * 16 + g;
            int e = ng * 32 + n * 8 + c2;
            *reinterpret_cast<float2*>(sc + tt * 66 + e) =
                make_float2(acc[n][0], acc[n][1]);
            *reinterpret_cast<float2*>(sc + (tt + 8) * 66 + e) =
                make_float2(acc[n][2], acc[n][3]);
        }
    }
    __syncthreads();

    if (tid < TB) {
        const int gt = t0 + tid;
        const float* row = sc + tid * 66;
        float w[NE], sv[NE];
#pragma unroll
        for (int e = 0; e < NE; e++) {
            float z = row[e] + bvec[e];
            w[e] = 1.0f / (1.0f + expf(-z));
            sv[e] = w[e] + bias[e];
        }
        float gs[NGRP];
#pragma unroll
        for (int g = 0; g < NGRP; g++) {
            float m1 = -1e30f, m2 = -1e30f;
#pragma unroll
            for (int j = 0; j < 8; j++) {
                float v = sv[8 * g + j];
                if (v > m1) { m2 = m1; m1 = v; }
                else if (v > m2) { m2 = v; }
            }
            gs[g] = m1 + m2;
        }
        int flag = 0;
        int gmask = 0;
        float v4 = 0.0f, v5 = 0.0f;
        for (int r = 0; r < 5; r++) {
            float bv = -1e30f; int bg = 0;
#pragma unroll
            for (int g = 0; g < NGRP; g++) {
                bool avail = !((gmask >> g) & 1);
                if (avail && gs[g] > bv) { bv = gs[g]; bg = g; }
            }
            if (r < 4) { gmask |= (1 << bg); v4 = bv; }
            else v5 = bv;
        }
        flag |= (v4 - v5) < GTAU;

        unsigned long long used = 0ull;
        float prev = 1e30f;
        for (int r = 0; r < 9; r++) {
            float bv = -1e30f, bw = 0.0f; int be = 0;
#pragma unroll
            for (int e = 0; e < NE; e++) {
                bool ok = ((gmask >> (e >> 3)) & 1) && !((used >> e) & 1ull);
                if (ok && sv[e] > bv) { bv = sv[e]; be = e; bw = w[e]; }
            }
            used |= (1ull << be);
            if (r < 8) {
                out[(size_t)gt * TOPK + r] = bw;
                out[(size_t)NTOK * TOPK + (size_t)gt * TOPK + r] = (float)be;
            }
            if (r > 0) flag |= (prev - bv) < ETAU;
            prev = bv;
        }
        if (flag) {
            unsigned int slot = atomicAdd(&g_redo_cnt, 1u);
            g_redo[slot] = (unsigned int)gt;
        }
    }
}

/* ------------- exact rescue (R12, proven): 4 tokens/CTA, 8 W phases ------------- */
__global__ void __launch_bounds__(256) redo_kernel(
    const float* __restrict__ x, const float* __restrict__ W,
    const float* __restrict__ bvec, const float* __restrict__ bias,
    float* __restrict__ out)
{
    extern __shared__ float rsm[];
    float* xs = rsm;
    float* ws = rsm + 4 * XSR2;
    __shared__ float zb[4][65];

    const unsigned int cnt = g_redo_cnt;
    if (blockIdx.x * 4u >= cnt) return;

    const int tid = threadIdx.x;
    const int e = tid >> 2;
    const int j = tid & 3;

    int ew[16], wc[16];
#pragma unroll
    for (int c = 0; c < 16; c++) {
        int f4 = tid + 256 * c;
        ew[c] = f4 >> 6;
        wc[c] = f4 & 63;
    }

    for (unsigned int base = blockIdx.x * 4u; base < cnt; base += gridDim.x * 4u) {
        int nt = (int)min(4u, cnt - base);
        __syncthreads();
        {
            int js = tid >> 6, li = tid & 63;
            if (js < nt) {
                const float4* xr = reinterpret_cast<const float4*>(
                    x + (size_t)g_redo[base + js] * DDIM);
                float4* xd = reinterpret_cast<float4*>(xs + js * XSR2);
#pragma unroll
                for (int c = 0; c < 8; c++) xd[li + 64 * c] = xr[li + 64 * c];
            }
        }
        float4 wreg[16];
#pragma unroll
        for (int c = 0; c < 16; c++)
            wreg[c] = *reinterpret_cast<const float4*>(
                W + (size_t)ew[c] * DDIM + 4 * wc[c]);
        __syncthreads();

        float acc = 0.0f;
#pragma unroll 1
        for (int t = 0; t < 8; t++) {
#pragma unroll
            for (int c = 0; c < 16; c++)
                *reinterpret_cast<float4*>(ws + ew[c] * WSR2 + 4 * wc[c]) = wreg[c];
            __syncthreads();

            if (t + 1 < 8) {
#pragma unroll
                for (int c = 0; c < 16; c++)
                    wreg[c] = *reinterpret_cast<const float4*>(
                        W + (size_t)ew[c] * DDIM + (t + 1) * 256 + 4 * wc[c]);
            }

            if (j < nt) {
                const float* xrow = xs + j * XSR2 + t * 256;
                const float* wrow = ws + e * WSR2;
#pragma unroll
                for (int k4 = 0; k4 < 64; k4++) {
                    float4 wq = *reinterpret_cast<const float4*>(wrow + 4 * k4);
                    float4 xq = *reinterpret_cast<const float4*>(xrow + 4 * k4);
                    acc = fmaf(xq.x, wq.x, acc);
                    acc = fmaf(xq.y, wq.y, acc);
                    acc = fmaf(xq.z, wq.z, acc);
                    acc = fmaf(xq.w, wq.w, acc);
                }
            }
            __syncthreads();
        }
        if (j < nt) zb[j][e] = acc + bvec[e];
        __syncthreads();

        if (tid < nt) {
            const int gt = (int)g_redo[base + tid];
            float w[NE], sv[NE];
#pragma unroll
            for (int ee = 0; ee < NE; ee++) {
                float z = zb[tid][ee];
                w[ee] = 1.0f / (1.0f + expf(-z));
                sv[ee] = w[ee] + bias[ee];
            }
            float gs[NGRP];
#pragma unroll
            for (int g = 0; g < NGRP; g++) {
                float m1 = -1e30f, m2 = -1e30f;
#pragma unroll
                for (int jj = 0; jj < 8; jj++) {
                    float v = sv[8 * g + jj];
                    if (v > m1) { m2 = m1; m1 = v; }
                    else if (v > m2) { m2 = v; }
                }
                gs[g] = m1 + m2;
            }
            int gmask = 0;
            for (int r = 0; r < TOPG; r++) {
                float bv = -1e30f; int bg = 0;
#pragma unroll
                for (int g = 0; g < NGRP; g++) {
                    bool avail = !((gmask >> g) & 1);
                    if (avail && gs[g] > bv) { bv = gs[g]; bg = g; }
                }
                gmask |= (1 << bg);
            }
            unsigned long long used = 0ull;
            for (int r = 0; r < TOPK; r++) {
                float bv = -1e30f, bw = 0.0f; int be = 0;
#pragma unroll
                for (int ee = 0; ee < NE; ee++) {
                    bool ok = ((gmask >> (ee >> 3)) & 1) && !((used >> ee) & 1ull);
                    if (ok && sv[ee] > bv) { bv = sv[ee]; be = ee; bw = w[ee]; }
                }
                used |= (1ull << be);
                out[(size_t)gt * TOPK + r] = bw;
                out[(size_t)NTOK * TOPK + (size_t)gt * TOPK + r] = (float)be;
            }
        }
    }
}

extern "C" void kernel_launch(void* const* d_in, const int* in_sizes, int n_in,
                              void* d_out, int out_size) {
    const float* x    = (const float*)d_in[0];
    const float* W    = (const float*)d_in[1];
    const float* b    = (const float*)d_in[2];
    const float* bias = (const float*)d_in[3];
    float* out = (float*)d_out;

    wsplit_kernel<<<256, 256>>>(W);
    cudaFuncSetAttribute(gate_gemm, cudaFuncAttributeMaxDynamicSharedMemorySize, SMEM_BYTES);
    gate_gemm<<<NB, 256, SMEM_BYTES>>>(x, b, bias, out);
    cudaFuncSetAttribute(redo_kernel, cudaFuncAttributeMaxDynamicSharedMemorySize, RSM_BYTES);
    redo_kernel<<<512, 256, RSM_BYTES>>>(x, W, b, bias, out);
}

// round 16
// speedup vs baseline: 1.0750x; 1.0750x over previous
#include <cuda_runtime.h>
#include <cuda_fp16.h>
#include <math.h>
#include <stdint.h>

#define NTOK 16384
#define DDIM 2048
#define NE   64
#define TOPK 8
#define TOPG 4
#define NGRP 8
#define TB   128
#define NB   (NTOK / TB)
#define KT   64
#define NTILE (DDIM / KT)
#define RW   36                    /* row stride in u32 (144 B) */
#define APL  (128 * RW)            /* A plane u32 = 4608 */
#define BPL  (64 * RW)             /* B plane u32 = 2304 */
#define BUFU (2 * APL + 2 * BPL)   /* 13824 u32 per buffer */
#define SMEM_BYTES (2 * BUFU * 4)  /* 110592 */

#define ETAU 2.0e-5f
#define GTAU 5.0e-5f

#define XSR2 2052
#define WSR2 260
#define RSM_BYTES ((4 * XSR2 + 64 * WSR2) * 4)  /* 99392 */
#define REDO_GRID 512

__device__ unsigned int g_redo_cnt;   /* zero-initialized at load; self-reset by redo */
__device__ unsigned int g_done;
__device__ unsigned int g_redo[NTOK];

/* ---------------- helpers ---------------- */
__device__ __forceinline__ uint32_t smem_u32(const void* p) {
    uint32_t a;
    asm("{ .reg .u64 t; cvta.to.shared.u64 t, %1; cvt.u32.u64 %0, t; }" : "=r"(a) : "l"(p));
    return a;
}
__device__ __forceinline__ void split2h(float a, float b, uint32_t& s0, uint32_t& s1) {
    __half2 h0 = __floats2half2_rn(a, b);
    float2 f0 = __half22float2(h0);
    __half2 h1 = __floats2half2_rn(a - f0.x, b - f0.y);
    s0 = *reinterpret_cast<uint32_t*>(&h0);
    s1 = *reinterpret_cast<uint32_t*>(&h1);
}
__device__ __forceinline__ void ldm4(uint32_t* r, uint32_t addr) {
    asm volatile("ldmatrix.sync.aligned.m8n8.x4.shared.b16 {%0,%1,%2,%3}, [%4];"
        : "=r"(r[0]), "=r"(r[1]), "=r"(r[2]), "=r"(r[3]) : "r"(addr));
}
__device__ __forceinline__ void mma16816(float* d, const uint32_t* a, const uint32_t* b) {
    asm volatile("mma.sync.aligned.m16n8k16.row.col.f32.f16.f16.f32 "
        "{%0,%1,%2,%3}, {%4,%5,%6,%7}, {%8,%9}, {%0,%1,%2,%3};"
        : "+f"(d[0]), "+f"(d[1]), "+f"(d[2]), "+f"(d[3])
        : "r"(a[0]), "r"(a[1]), "r"(a[2]), "r"(a[3]), "r"(b[0]), "r"(b[1]));
}

/* ------------- fast path: fp16-split mma GEMM, inline W convert ------------- */
__global__ void __launch_bounds__(256) gate_gemm(
    const float* __restrict__ x, const float* __restrict__ W,
    const float* __restrict__ bvec, const float* __restrict__ bias,
    float* __restrict__ out)
{
    extern __shared__ uint32_t sm[];
    const uint32_t smb = smem_u32(sm);
    const int tid = threadIdx.x;
    const int lane = tid & 31, wid = tid >> 5;
    const int t0 = blockIdx.x * TB;

    const int kq = tid & 15;
    const int tb = tid >> 4;
    const float4* xp[8];
    int aoff[8];
#pragma unroll
    for (int j = 0; j < 8; j++) {
        int t = tb + 16 * j;
        xp[j] = reinterpret_cast<const float4*>(x + (size_t)(t0 + t) * DDIM + 4 * kq);
        aoff[j] = t * RW + 2 * kq;
    }
    /* W loaders: 4 chunks cover 64 experts x 16 k-quads (fp32 source) */
    const float4* wp[4];
    int eoff[4];
#pragma unroll
    for (int c = 0; c < 4; c++) {
        int idx = tid + 256 * c;       /* 0..1023 */
        int e = idx >> 4, q = idx & 15;
        wp[c] = reinterpret_cast<const float4*>(W + (size_t)e * DDIM + 4 * q);
        eoff[c] = 2 * APL + e * RW + 2 * q;
    }

    const int mg = wid >> 1, ng = wid & 1;
    const uint32_t aLM0 = smb + (uint32_t)(lane & 15) * 144u + (uint32_t)(lane >> 4) * 16u;
    const uint32_t bLM0 = smb + 2u * APL * 4u + (uint32_t)((lane >> 4) & 1) * 1152u
                        + (uint32_t)(lane & 7) * 144u + (uint32_t)((lane >> 3) & 1) * 16u;

    float acc[2][4][4];
#pragma unroll
    for (int m = 0; m < 2; m++)
#pragma unroll
        for (int n = 0; n < 4; n++)
#pragma unroll
            for (int q = 0; q < 4; q++) acc[m][n][q] = 0.0f;

    float4 xv[8], wv[4];
#pragma unroll
    for (int j = 0; j < 8; j++) xv[j] = xp[j][0];
#pragma unroll
    for (int c = 0; c < 4; c++) wv[c] = wp[c][0];

    /* STS tile 0 -> buf0 (x and W both split to fp16 planes) */
    {
        uint32_t* bp = sm;
#pragma unroll
        for (int j = 0; j < 8; j++) {
            uint32_t p0, p1, q0, q1;
            split2h(xv[j].x, xv[j].y, p0, p1);
            split2h(xv[j].z, xv[j].w, q0, q1);
            uint32_t* ap = bp + aoff[j];
            *reinterpret_cast<uint2*>(ap)       = make_uint2(p0, q0);
            *reinterpret_cast<uint2*>(ap + APL) = make_uint2(p1, q1);
        }
#pragma unroll
        for (int c = 0; c < 4; c++) {
            uint32_t s0a, s1a, s0b, s1b;
            split2h(wv[c].x, wv[c].y, s0a, s1a);
            split2h(wv[c].z, wv[c].w, s0b, s1b);
            uint32_t* wpB = bp + eoff[c];
            *reinterpret_cast<uint2*>(wpB)       = make_uint2(s0a, s0b);
            *reinterpret_cast<uint2*>(wpB + BPL) = make_uint2(s1a, s1b);
        }
    }
    __syncthreads();

#pragma unroll 1
    for (int t = 0; t < NTILE; t++) {
        const int cur = t & 1;
        const uint32_t bofs = (uint32_t)cur * (BUFU * 4u);

        /* issue LDG for tile t+1 (hides under mma phase) */
        if (t + 1 < NTILE) {
#pragma unroll
            for (int j = 0; j < 8; j++) { xp[j] += 16; xv[j] = xp[j][0]; }
#pragma unroll
            for (int c = 0; c < 4; c++) { wp[c] += 16; wv[c] = wp[c][0]; }
        }

        /* mma phase on buf[cur] — R8/R14 ordering (do not touch) */
#pragma unroll
        for (int k16 = 0; k16 < 4; k16++) {
            uint32_t a[2][2][4];
#pragma unroll
            for (int m = 0; m < 2; m++)
#pragma unroll
                for (int s = 0; s < 2; s++)
                    ldm4(a[m][s], aLM0 + bofs + (uint32_t)s * (APL * 4u)
                                + (uint32_t)(mg * 32 + m * 16) * 144u + (uint32_t)k16 * 32u);
            uint32_t b[4][2][2];
#pragma unroll
            for (int p = 0; p < 2; p++)
#pragma unroll
                for (int s = 0; s < 2; s++) {
                    uint32_t r[4];
                    ldm4(r, bLM0 + bofs + (uint32_t)s * (BPL * 4u)
                           + (uint32_t)(ng * 4 + 2 * p) * 1152u + (uint32_t)k16 * 32u);
                    b[2 * p][s][0] = r[0]; b[2 * p][s][1] = r[1];
                    b[2 * p + 1][s][0] = r[2]; b[2 * p + 1][s][1] = r[3];
                }
#pragma unroll
            for (int m = 0; m < 2; m++)
#pragma unroll
                for (int n = 0; n < 4; n++) {
                    float* d = acc[m][n];
                    mma16816(d, a[m][0], b[n][0]);
                    mma16816(d, a[m][0], b[n][1]);
                    mma16816(d, a[m][1], b[n][0]);
                }
        }

        /* STS tile t+1 -> other buffer */
        if (t + 1 < NTILE) {
            uint32_t* bp = sm + (1 - cur) * BUFU;
#pragma unroll
            for (int j = 0; j < 8; j++) {
                uint32_t p0, p1, q0, q1;
                split2h(xv[j].x, xv[j].y, p0, p1);
                split2h(xv[j].z, xv[j].w, q0, q1);
                uint32_t* ap = bp + aoff[j];
                *reinterpret_cast<uint2*>(ap)       = make_uint2(p0, q0);
                *reinterpret_cast<uint2*>(ap + APL) = make_uint2(p1, q1);
            }
#pragma unroll
            for (int c = 0; c < 4; c++) {
                uint32_t s0a, s1a, s0b, s1b;
                split2h(wv[c].x, wv[c].y, s0a, s1a);
                split2h(wv[c].z, wv[c].w, s0b, s1b);
                uint32_t* wpB = bp + eoff[c];
                *reinterpret_cast<uint2*>(wpB)       = make_uint2(s0a, s0b);
                *reinterpret_cast<uint2*>(wpB + BPL) = make_uint2(s1a, s1b);
            }
        }
        __syncthreads();
    }

    /* logits -> sc[token][expert], stride 66 */
    float* sc = reinterpret_cast<float*>(sm);
    {
        const int g = lane >> 2, c2 = 2 * (lane & 3);
#pragma unroll
        for (int m = 0; m < 2; m++)
#pragma unroll
            for (int n = 0; n < 4; n++) {
                int tt = mg * 32 + m * 16 + g;
                int e = ng * 32 + n * 8 + c2;
                *reinterpret_cast<float2*>(sc + tt * 66 + e) =
                    make_float2(acc[m][n][0], acc[m][n][1]);
                *reinterpret_cast<float2*>(sc + (tt + 8) * 66 + e) =
                    make_float2(acc[m][n][2], acc[m][n][3]);
            }
    }
    __syncthreads();

    if (tid < TB) {
        const int gt = t0 + tid;
        const float* row = sc + tid * 66;
        float w[NE], sv[NE];
#pragma unroll
        for (int e = 0; e < NE; e++) {
            float z = row[e] + bvec[e];
            w[e] = 1.0f / (1.0f + expf(-z));
            sv[e] = w[e] + bias[e];
        }
        float gs[NGRP];
#pragma unroll
        for (int g = 0; g < NGRP; g++) {
            float m1 = -1e30f, m2 = -1e30f;
#pragma unroll
            for (int j = 0; j < 8; j++) {
                float v = sv[8 * g + j];
                if (v > m1) { m2 = m1; m1 = v; }
                else if (v > m2) { m2 = v; }
            }
            gs[g] = m1 + m2;
        }
        int flag = 0;
        int gmask = 0;
        float v4 = 0.0f, v5 = 0.0f;
        for (int r = 0; r < 5; r++) {
            float bv = -1e30f; int bg = 0;
#pragma unroll
            for (int g = 0; g < NGRP; g++) {
                bool avail = !((gmask >> g) & 1);
                if (avail && gs[g] > bv) { bv = gs[g]; bg = g; }
            }
            if (r < 4) { gmask |= (1 << bg); v4 = bv; }
            else v5 = bv;
        }
        flag |= (v4 - v5) < GTAU;

        unsigned long long used = 0ull;
        float prev = 1e30f;
        for (int r = 0; r < 9; r++) {
            float bv = -1e30f, bw = 0.0f; int be = 0;
#pragma unroll
            for (int e = 0; e < NE; e++) {
                bool ok = ((gmask >> (e >> 3)) & 1) && !((used >> e) & 1ull);
                if (ok && sv[e] > bv) { bv = sv[e]; be = e; bw = w[e]; }
            }
            used |= (1ull << be);
            if (r < 8) {
                out[(size_t)gt * TOPK + r] = bw;
                out[(size_t)NTOK * TOPK + (size_t)gt * TOPK + r] = (float)be;
            }
            if (r > 0) flag |= (prev - bv) < ETAU;
            prev = bv;
        }
        if (flag) {
            unsigned int slot = atomicAdd(&g_redo_cnt, 1u);
            g_redo[slot] = (unsigned int)gt;
        }
    }
}

/* ------------- exact rescue (R12 body) + counter self-reset ------------- */
__global__ void __launch_bounds__(256) redo_kernel(
    const float* __restrict__ x, const float* __restrict__ W,
    const float* __restrict__ bvec, const float* __restrict__ bias,
    float* __restrict__ out)
{
    extern __shared__ float rsm[];
    float* xs = rsm;
    float* ws = rsm + 4 * XSR2;
    __shared__ float zb[4][65];

    const unsigned int cnt = g_redo_cnt;
    const int tid = threadIdx.x;
    const int e = tid >> 2;
    const int j = tid & 3;

    int ew[16], wc[16];
#pragma unroll
    for (int c = 0; c < 16; c++) {
        int f4 = tid + 256 * c;
        ew[c] = f4 >> 6;
        wc[c] = f4 & 63;
    }

    for (unsigned int base = blockIdx.x * 4u; base < cnt; base += gridDim.x * 4u) {
        int nt = (int)min(4u, cnt - base);
        __syncthreads();
        {
            int js = tid >> 6, li = tid & 63;
            if (js < nt) {
                const float4* xr = reinterpret_cast<const float4*>(
                    x + (size_t)g_redo[base + js] * DDIM);
                float4* xd = reinterpret_cast<float4*>(xs + js * XSR2);
#pragma unroll
                for (int c = 0; c < 8; c++) xd[li + 64 * c] = xr[li + 64 * c];
            }
        }
        float4 wreg[16];
#pragma unroll
        for (int c = 0; c < 16; c++)
            wreg[c] = *reinterpret_cast<const float4*>(
                W + (size_t)ew[c] * DDIM + 4 * wc[c]);
        __syncthreads();

        float acc = 0.0f;
#pragma unroll 1
        for (int t = 0; t < 8; t++) {
#pragma unroll
            for (int c = 0; c < 16; c++)
                *reinterpret_cast<float4*>(ws + ew[c] * WSR2 + 4 * wc[c]) = wreg[c];
            __syncthreads();

            if (t + 1 < 8) {
#pragma unroll
                for (int c = 0; c < 16; c++)
                    wreg[c] = *reinterpret_cast<const float4*>(
                        W + (size_t)ew[c] * DDIM + (t + 1) * 256 + 4 * wc[c]);
            }

            if (j < nt) {
                const float* xrow = xs + j * XSR2 + t * 256;
                const float* wrow = ws + e * WSR2;
#pragma unroll
                for (int k4 = 0; k4 < 64; k4++) {
                    float4 wq = *reinterpret_cast<const float4*>(wrow + 4 * k4);
                    float4 xq = *reinterpret_cast<const float4*>(xrow + 4 * k4);
                    acc = fmaf(xq.x, wq.x, acc);
                    acc = fmaf(xq.y, wq.y, acc);
                    acc = fmaf(xq.z, wq.z, acc);
                    acc = fmaf(xq.w, wq.w, acc);
                }
            }
            __syncthreads();
        }
        if (j < nt) zb[j][e] = acc + bvec[e];
        __syncthreads();

        if (tid < nt) {
            const int gt = (int)g_redo[base + tid];
            float w[NE], sv[NE];
#pragma unroll
            for (int ee = 0; ee < NE; ee++) {
                float z = zb[tid][ee];
                w[ee] = 1.0f / (1.0f + expf(-z));
                sv[ee] = w[ee] + bias[ee];
            }
            float gs[NGRP];
#pragma unroll
            for (int g = 0; g < NGRP; g++) {
                float m1 = -1e30f, m2 = -1e30f;
#pragma unroll
                for (int jj = 0; jj < 8; jj++) {
                    float v = sv[8 * g + jj];
                    if (v > m1) { m2 = m1; m1 = v; }
                    else if (v > m2) { m2 = v; }
                }
                gs[g] = m1 + m2;
            }
            int gmask = 0;
            for (int r = 0; r < TOPG; r++) {
                float bv = -1e30f; int bg = 0;
#pragma unroll
                for (int g = 0; g < NGRP; g++) {
                    bool avail = !((gmask >> g) & 1);
                    if (avail && gs[g] > bv) { bv = gs[g]; bg = g; }
                }
                gmask |= (1 << bg);
            }
            unsigned long long used = 0ull;
            for (int r = 0; r < TOPK; r++) {
                float bv = -1e30f, bw = 0.0f; int be = 0;
#pragma unroll
                for (int ee = 0; ee < NE; ee++) {
                    bool ok = ((gmask >> (ee >> 3)) & 1) && !((used >> ee) & 1ull);
                    if (ok && sv[ee] > bv) { bv = sv[ee]; be = ee; bw = w[ee]; }
                }
                used |= (1ull << be);
                out[(size_t)gt * TOPK + r] = bw;
                out[(size_t)NTOK * TOPK + (size_t)gt * TOPK + r] = (float)be;
            }
        }
    }

    /* self-reset for next launch: last CTA to finish clears the counters */
    __threadfence();
    __syncthreads();
    if (tid == 0) {
        unsigned int old = atomicAdd(&g_done, 1u);
        if (old == gridDim.x - 1) {
            g_redo_cnt = 0;
            g_done = 0;
            __threadfence();
        }
    }
}

extern "C" void kernel_launch(void* const* d_in, const int* in_sizes, int n_in,
                              void* d_out, int out_size) {
    const float* x    = (const float*)d_in[0];
    const float* W    = (const float*)d_in[1];
    const float* b    = (const float*)d_in[2];
    const float* bias = (const float*)d_in[3];
    float* out = (float*)d_out;

    cudaFuncSetAttribute(gate_gemm, cudaFuncAttributeMaxDynamicSharedMemorySize, SMEM_BYTES);
    gate_gemm<<<NB, 256, SMEM_BYTES>>>(x, W, b, bias, out);
    cudaFuncSetAttribute(redo_kernel, cudaFuncAttributeMaxDynamicSharedMemorySize, RSM_BYTES);
    redo_kernel<<<REDO_GRID, 256, RSM_BYTES>>>(x, W, b, bias, out);
}